// round 3
// baseline (speedup 1.0000x reference)
#include <cuda_runtime.h>
#include <math.h>

#define FULL 0xffffffffu
#define BB   16
#define TT   1024
#define HHID 1024
#define SS   32
#define CC   3
#define NHH  16
#define DHH  64
#define HH2  512
#define G4   2048

// ---------------- scratch ----------------
__device__ float g_xs_f[BB*TT*G4];
__device__ float g_xs_b[BB*TT*G4];
__device__ float g_enc [BB*TT*HHID];
__device__ float g_hbuf[2][2][BB][HH2];
__device__ float g_feat [BB*SS*HHID];
__device__ float g_q    [BB*SS*HHID];
__device__ float g_k    [BB*SS*HHID];
__device__ float g_v    [BB*SS*HHID];
__device__ float g_ctx  [BB*SS*HHID];
__device__ float g_ao   [BB*SS*HHID];
__device__ float g_feat2[BB*SS*HHID];
__device__ float g_terms[BB*SS*4];
__device__ unsigned g_bar_count = 0;
__device__ unsigned g_bar_gen   = 0;

// ---------------- grid-wide barrier ----------------
__device__ __forceinline__ void grid_barrier(unsigned nblocks)
{
    __syncthreads();
    if (threadIdx.x == 0) {
        volatile unsigned* genp = &g_bar_gen;
        const unsigned gen = *genp;
        __threadfence();
        const unsigned arrived = atomicAdd(&g_bar_count, 1u);
        if (arrived == nblocks - 1u) {
            atomicExch(&g_bar_count, 0u);
            __threadfence();
            atomicExch(&g_bar_gen, gen + 1u);
        } else {
            while (*genp == gen) { __nanosleep(32); }
            __threadfence();
        }
    }
    __syncthreads();
}

// ---------------- register-tiled SGEMM ----------------
// C[M,N] = A[M,K] * op(B) + bias[N].
// TRANS_B: B is (N,K) row-major; else (K,N) row-major.
// BM=BN=128, BK=8, TM=TN=8, 256 threads.
template<bool TRANS_B>
__global__ void __launch_bounds__(256)
sgemm_kernel(const float* __restrict__ A, const float* __restrict__ B,
             const float* __restrict__ bias, float* __restrict__ C,
             int M, int N, int K)
{
    const int BM = 128, BN = 128, BK = 8, TM = 8, TN = 8;
    __shared__ float As[BK][BM];
    __shared__ float Bs[BK][BN];
    const int tid = threadIdx.x;
    const int bm = blockIdx.y * BM;
    const int bn = blockIdx.x * BN;
    const int tx = tid & 15;
    const int ty = tid >> 4;

    float acc[TM][TN];
#pragma unroll
    for (int i = 0; i < TM; i++)
#pragma unroll
        for (int j = 0; j < TN; j++) acc[i][j] = 0.f;

    const int aRow = (tid * 4) / BK;
    const int aCol = (tid * 4) % BK;
    int bRow, bCol;
    if (TRANS_B) { bRow = (tid * 4) / BK; bCol = (tid * 4) % BK; }
    else         { bRow = (tid * 4) / BN; bCol = (tid * 4) % BN; }

    const float* Aptr = A + (size_t)(bm + aRow) * K + aCol;
    const float* Bptr;
    if (TRANS_B) Bptr = B + (size_t)(bn + bRow) * K + bCol;
    else         Bptr = B + (size_t)bRow * N + (bn + bCol);

    for (int k0 = 0; k0 < K; k0 += BK) {
        const float4 av = *(const float4*)Aptr; Aptr += BK;
        As[aCol + 0][aRow] = av.x;
        As[aCol + 1][aRow] = av.y;
        As[aCol + 2][aRow] = av.z;
        As[aCol + 3][aRow] = av.w;
        if (TRANS_B) {
            const float4 bv = *(const float4*)Bptr; Bptr += BK;
            Bs[bCol + 0][bRow] = bv.x;
            Bs[bCol + 1][bRow] = bv.y;
            Bs[bCol + 2][bRow] = bv.z;
            Bs[bCol + 3][bRow] = bv.w;
        } else {
            const float4 bv = *(const float4*)Bptr; Bptr += (size_t)BK * N;
            *(float4*)&Bs[bRow][bCol] = bv;
        }
        __syncthreads();
#pragma unroll
        for (int kk = 0; kk < BK; kk++) {
            float ar[TM], br[TN];
#pragma unroll
            for (int h = 0; h < 2; h++) {
                const float4 t4 = *(const float4*)&As[kk][h * 64 + ty * 4];
                ar[h*4+0]=t4.x; ar[h*4+1]=t4.y; ar[h*4+2]=t4.z; ar[h*4+3]=t4.w;
            }
#pragma unroll
            for (int h = 0; h < 2; h++) {
                const float4 t4 = *(const float4*)&Bs[kk][h * 64 + tx * 4];
                br[h*4+0]=t4.x; br[h*4+1]=t4.y; br[h*4+2]=t4.z; br[h*4+3]=t4.w;
            }
#pragma unroll
            for (int i = 0; i < TM; i++)
#pragma unroll
                for (int j = 0; j < TN; j++)
                    acc[i][j] += ar[i] * br[j];
        }
        __syncthreads();
    }

#pragma unroll
    for (int i = 0; i < TM; i++) {
        const int row = bm + (i / 4) * 64 + ty * 4 + (i % 4);
#pragma unroll
        for (int j = 0; j < TN; j++) {
            const int col = bn + (j / 4) * 64 + tx * 4 + (j % 4);
            C[(size_t)row * N + col] = acc[i][j] + bias[col];
        }
    }
}

// ---------------- persistent bidirectional LSTM scan ----------------
// 128 CTAs x 256 thr. dir = cid>>6; CTA owns 8 units; warp w -> unit.
// lane = gt*8 + kc (gate, k-chunk). Whh row in 64 regs.
__global__ void __launch_bounds__(256)
lstm_scan_kernel(const float* __restrict__ Whh_f, const float* __restrict__ Whh_b)
{
    const int cid  = blockIdx.x;
    const int dir  = cid >> 6;
    const int ug   = cid & 63;
    const int warp = threadIdx.x >> 5;
    const int lane = threadIdx.x & 31;
    const int gt   = lane >> 3;
    const int kc   = lane & 7;
    const int u    = ug * 8 + warp;
    const int grow = gt * HH2 + u;

    const float* __restrict__ Whh = dir ? Whh_b : Whh_f;
    const float* __restrict__ xs  = dir ? g_xs_b : g_xs_f;

    float4 w[16];
#pragma unroll
    for (int j = 0; j < 16; j++)
        w[j] = *(const float4*)&Whh[(size_t)grow * HH2 + (kc + 8 * j) * 4];

    __shared__ float h_sh[BB][HH2];

    float c_state[BB];
#pragma unroll
    for (int b = 0; b < BB; b++) c_state[b] = 0.f;

    const unsigned nblk = gridDim.x;

    for (int s = 0; s < TT; s++) {
        const int t = dir ? (TT - 1 - s) : s;

        if (s == 0) {
            for (int i = threadIdx.x; i < BB * HH2; i += 256)
                ((float*)h_sh)[i] = 0.f;
        } else {
            const float* hg = &g_hbuf[dir][(s - 1) & 1][0][0];
            for (int i = threadIdx.x * 4; i < BB * HH2; i += 1024)
                *(float4*)&((float*)h_sh)[i] = *(const float4*)&hg[i];
        }

        float xsv[BB];
        if (kc == 0) {
#pragma unroll
            for (int b = 0; b < BB; b++)
                xsv[b] = xs[(size_t)(b * TT + t) * G4 + grow];
        }
        __syncthreads();

        float acc[BB];
#pragma unroll
        for (int b = 0; b < BB; b++) acc[b] = 0.f;

#pragma unroll
        for (int j = 0; j < 16; j++) {
            const int kbase = (kc + 8 * j) * 4;
#pragma unroll
            for (int b = 0; b < BB; b++) {
                const float4 hv = *(const float4*)&h_sh[b][kbase];
                acc[b] += w[j].x * hv.x;
                acc[b] += w[j].y * hv.y;
                acc[b] += w[j].z * hv.z;
                acc[b] += w[j].w * hv.w;
            }
        }

#pragma unroll
        for (int b = 0; b < BB; b++) {
            acc[b] += __shfl_down_sync(FULL, acc[b], 4);
            acc[b] += __shfl_down_sync(FULL, acc[b], 2);
            acc[b] += __shfl_down_sync(FULL, acc[b], 1);
        }

        float gv[BB];
#pragma unroll
        for (int b = 0; b < BB; b++) gv[b] = 0.f;
        if (kc == 0) {
#pragma unroll
            for (int b = 0; b < BB; b++) {
                const float x = acc[b] + xsv[b];
                gv[b] = (gt == 2) ? tanhf(x) : (1.f / (1.f + expf(-x)));
            }
        }

#pragma unroll
        for (int b = 0; b < BB; b++) {
            const float iv = __shfl_sync(FULL, gv[b], 0);
            const float fv = __shfl_sync(FULL, gv[b], 8);
            const float gg = __shfl_sync(FULL, gv[b], 16);
            const float ov = __shfl_sync(FULL, gv[b], 24);
            if (lane == 0) {
                const float cn = fv * c_state[b] + iv * gg;
                c_state[b] = cn;
                const float hn = ov * tanhf(cn);
                g_hbuf[dir][s & 1][b][u] = hn;
                g_enc[(size_t)(b * TT + t) * HHID + dir * HH2 + u] = hn;
            }
        }

        grid_barrier(nblk);
    }
}

// ---------------- span mean-pool + LayerNorm ----------------
__global__ void __launch_bounds__(256)
span_pool_ln_kernel(const int* __restrict__ heads, const int* __restrict__ tails,
                    const float* __restrict__ lng, const float* __restrict__ lnb)
{
    const int r = blockIdx.x;
    const int b = r >> 5;
    int p0 = heads[r] + 1; if (p0 < 0) p0 = 0;
    int p1 = tails[r];     if (p1 > TT) p1 = TT;
    const int tid = threadIdx.x;
    const int d = tid * 4;

    float s0=0,s1=0,s2=0,s3=0;
    for (int p = p0; p < p1; p++) {
        const float4 vv = *(const float4*)&g_enc[(size_t)(b * TT + p) * HHID + d];
        s0 += vv.x; s1 += vv.y; s2 += vv.z; s3 += vv.w;
    }
    int cnt = p1 - p0; if (cnt < 1) cnt = 1;
    const float inv = 1.f / (float)cnt;
    const float v0=s0*inv, v1=s1*inv, v2=s2*inv, v3=s3*inv;

    __shared__ float red[256];
    __shared__ float stats[2];
    red[tid] = v0+v1+v2+v3;
    __syncthreads();
    for (int st = 128; st > 0; st >>= 1) { if (tid < st) red[tid] += red[tid+st]; __syncthreads(); }
    if (tid == 0) stats[0] = red[0] * (1.f / HHID);
    __syncthreads();
    const float mean = stats[0];
    const float q0=v0-mean, q1=v1-mean, q2=v2-mean, q3=v3-mean;
    red[tid] = q0*q0+q1*q1+q2*q2+q3*q3;
    __syncthreads();
    for (int st = 128; st > 0; st >>= 1) { if (tid < st) red[tid] += red[tid+st]; __syncthreads(); }
    if (tid == 0) stats[1] = rsqrtf(red[0] * (1.f / HHID) + 1e-7f);
    __syncthreads();
    const float rstd = stats[1];
    float* out = &g_feat[(size_t)r * HHID + d];
    out[0] = q0*rstd*lng[d+0] + lnb[d+0];
    out[1] = q1*rstd*lng[d+1] + lnb[d+1];
    out[2] = q2*rstd*lng[d+2] + lnb[d+2];
    out[3] = q3*rstd*lng[d+3] + lnb[d+3];
}

// ---------------- attention ----------------
__global__ void __launch_bounds__(256)
attn_kernel(const int* __restrict__ am)
{
    const int bh = blockIdx.x;
    const int b = bh >> 4;
    const int h = bh & 15;
    __shared__ float qs[SS][DHH], ks[SS][DHH], vs[SS][DHH];
    __shared__ float sc[SS][SS + 1];
    const int tid = threadIdx.x;

    for (int i = tid; i < SS * DHH; i += 256) {
        const int s = i >> 6, d = i & 63;
        const size_t off = (size_t)(b * SS + s) * HHID + h * DHH + d;
        qs[s][d] = g_q[off];
        ks[s][d] = g_k[off];
        vs[s][d] = g_v[off];
    }
    __syncthreads();

    for (int i = tid; i < SS * SS; i += 256) {
        const int qq = i >> 5, kk = i & 31;
        float a = 0.f;
#pragma unroll
        for (int d = 0; d < DHH; d++) a += qs[qq][d] * ks[kk][d];
        const bool valid = (am[b * SS + qq] != 0) && (am[b * SS + kk] != 0);
        sc[qq][kk] = valid ? a * 0.125f : -1e9f;
    }
    __syncthreads();

    const int wid = tid >> 5, lane = tid & 31;
    for (int r = wid; r < SS; r += 8) {
        const float val = sc[r][lane];
        float m = val;
#pragma unroll
        for (int o = 16; o > 0; o >>= 1) m = fmaxf(m, __shfl_xor_sync(FULL, m, o));
        const float e = expf(val - m);
        float sum = e;
#pragma unroll
        for (int o = 16; o > 0; o >>= 1) sum += __shfl_xor_sync(FULL, sum, o);
        sc[r][lane] = e / sum;
    }
    __syncthreads();

    for (int i = tid; i < SS * DHH; i += 256) {
        const int qq = i >> 6, d = i & 63;
        float a = 0.f;
#pragma unroll
        for (int kk = 0; kk < SS; kk++) a += sc[qq][kk] * vs[kk][d];
        g_ctx[(size_t)(b * SS + qq) * HHID + h * DHH + d] = a;
    }
}

// ---------------- residual + LayerNorm ----------------
__global__ void __launch_bounds__(256)
resid_ln_kernel(const float* __restrict__ lng, const float* __restrict__ lnb)
{
    const int r = blockIdx.x;
    const int tid = threadIdx.x;
    const int d = tid * 4;
    const size_t base = (size_t)r * HHID + d;
    const float4 a = *(const float4*)&g_ao[base];
    const float4 f = *(const float4*)&g_feat[base];
    const float v0=a.x+f.x, v1=a.y+f.y, v2=a.z+f.z, v3=a.w+f.w;

    __shared__ float red[256];
    __shared__ float stats[2];
    red[tid] = v0+v1+v2+v3;
    __syncthreads();
    for (int st = 128; st > 0; st >>= 1) { if (tid < st) red[tid] += red[tid+st]; __syncthreads(); }
    if (tid == 0) stats[0] = red[0] * (1.f / HHID);
    __syncthreads();
    const float mean = stats[0];
    const float q0=v0-mean, q1=v1-mean, q2=v2-mean, q3=v3-mean;
    red[tid] = q0*q0+q1*q1+q2*q2+q3*q3;
    __syncthreads();
    for (int st = 128; st > 0; st >>= 1) { if (tid < st) red[tid] += red[tid+st]; __syncthreads(); }
    if (tid == 0) stats[1] = rsqrtf(red[0] * (1.f / HHID) + 1e-7f);
    __syncthreads();
    const float rstd = stats[1];
    float* out = &g_feat2[base];
    out[0] = q0*rstd*lng[d+0] + lnb[d+0];
    out[1] = q1*rstd*lng[d+1] + lnb[d+1];
    out[2] = q2*rstd*lng[d+2] + lnb[d+2];
    out[3] = q3*rstd*lng[d+3] + lnb[d+3];
}

// ---------------- classifier + per-span loss terms ----------------
__global__ void __launch_bounds__(128)
loss_terms_kernel(const int* __restrict__ labels, const float* __restrict__ wf,
                  const int* __restrict__ am,
                  const float* __restrict__ Wc, const float* __restrict__ bc)
{
    const int r = blockIdx.x;
    const int tid = threadIdx.x;
    const float* row = &g_feat2[(size_t)r * HHID];
    float d0=0, d1=0, d2=0;
    for (int i = tid; i < HHID; i += 128) {
        const float x = row[i];
        d0 += x * Wc[i*3+0];
        d1 += x * Wc[i*3+1];
        d2 += x * Wc[i*3+2];
    }
    __shared__ float r0[128], r1[128], r2[128];
    r0[tid]=d0; r1[tid]=d1; r2[tid]=d2;
    __syncthreads();
    for (int st = 64; st > 0; st >>= 1) {
        if (tid < st) { r0[tid]+=r0[tid+st]; r1[tid]+=r1[tid+st]; r2[tid]+=r2[tid+st]; }
        __syncthreads();
    }
    if (tid == 0) {
        const float z0 = r0[0]+bc[0], z1 = r1[0]+bc[1], z2 = r2[0]+bc[2];
        const float m = fmaxf(z0, fmaxf(z1, z2));
        const float e0 = expf(z0-m), e1 = expf(z1-m), e2 = expf(z2-m);
        const float lse = m + logf(e0+e1+e2);
        const int lab = labels[r];
        const bool valid = lab >= 0;
        const int lc = valid ? lab : 0;
        const float zl = (lc==0) ? z0 : ((lc==1) ? z1 : z2);
        const float logp = zl - lse;
        const float pt = expf(logp);
        const float spanm = ((am[r]!=0) && valid) ? 1.f : 0.f;
        const float vm = valid ? 1.f : 0.f;
        const float omp = 1.f - pt;
        g_terms[r*4+0] = (-logp * wf[r]) * spanm;
        g_terms[r*4+1] = spanm;
        g_terms[r*4+2] = (-(omp*omp) * logp) * vm;
        g_terms[r*4+3] = vm;
    }
}

__global__ void __launch_bounds__(256)
final_loss_kernel(float* __restrict__ out)
{
    const int tid = threadIdx.x;
    float a0=0,a1=0,a2=0,a3=0;
    for (int r = tid; r < BB*SS; r += 256) {
        a0 += g_terms[r*4+0]; a1 += g_terms[r*4+1];
        a2 += g_terms[r*4+2]; a3 += g_terms[r*4+3];
    }
    __shared__ float s0[256], s1[256], s2[256], s3[256];
    s0[tid]=a0; s1[tid]=a1; s2[tid]=a2; s3[tid]=a3;
    __syncthreads();
    for (int st = 128; st > 0; st >>= 1) {
        if (tid < st) { s0[tid]+=s0[tid+st]; s1[tid]+=s1[tid+st]; s2[tid]+=s2[tid+st]; s3[tid]+=s3[tid+st]; }
        __syncthreads();
    }
    if (tid == 0)
        out[0] = s0[0] / fmaxf(s1[0], 1.f) + s2[0] / fmaxf(s3[0], 1.f);
}

// ---------------- launch ----------------
extern "C" void kernel_launch(void* const* d_in, const int* in_sizes, int n_in,
                              void* d_out, int out_size)
{
    const float* hs     = (const float*)d_in[0];
    const int*   heads  = (const int*)  d_in[1];
    const int*   tails  = (const int*)  d_in[2];
    const int*   am     = (const int*)  d_in[3];
    const int*   labels = (const int*)  d_in[4];
    const float* wf     = (const float*)d_in[5];
    const float* Wih_f  = (const float*)d_in[6];
    const float* Whh_f  = (const float*)d_in[7];
    const float* b_f    = (const float*)d_in[8];
    const float* Wih_b  = (const float*)d_in[9];
    const float* Whh_b  = (const float*)d_in[10];
    const float* b_b    = (const float*)d_in[11];
    const float* ln1g   = (const float*)d_in[12];
    const float* ln1b   = (const float*)d_in[13];
    const float* Wq     = (const float*)d_in[14];
    const float* bq     = (const float*)d_in[15];
    const float* Wk     = (const float*)d_in[16];
    const float* bk     = (const float*)d_in[17];
    const float* Wv     = (const float*)d_in[18];
    const float* bv     = (const float*)d_in[19];
    const float* Wo     = (const float*)d_in[20];
    const float* bo     = (const float*)d_in[21];
    const float* ln2g   = (const float*)d_in[22];
    const float* ln2b   = (const float*)d_in[23];
    const float* Wc     = (const float*)d_in[24];
    const float* bc     = (const float*)d_in[25];

    float *p_xs_f, *p_xs_b, *p_feat, *p_q, *p_k, *p_v, *p_ctx, *p_ao, *p_feat2;
    cudaGetSymbolAddress((void**)&p_xs_f,  g_xs_f);
    cudaGetSymbolAddress((void**)&p_xs_b,  g_xs_b);
    cudaGetSymbolAddress((void**)&p_feat,  g_feat);
    cudaGetSymbolAddress((void**)&p_q,     g_q);
    cudaGetSymbolAddress((void**)&p_k,     g_k);
    cudaGetSymbolAddress((void**)&p_v,     g_v);
    cudaGetSymbolAddress((void**)&p_ctx,   g_ctx);
    cudaGetSymbolAddress((void**)&p_ao,    g_ao);
    cudaGetSymbolAddress((void**)&p_feat2, g_feat2);

    // input projections: [16384,1024] x [2048,1024]^T
    {
        dim3 grid(G4/128, (BB*TT)/128), blk(256);
        sgemm_kernel<true><<<grid, blk>>>(hs, Wih_f, b_f, p_xs_f, BB*TT, G4, HHID);
        sgemm_kernel<true><<<grid, blk>>>(hs, Wih_b, b_b, p_xs_b, BB*TT, G4, HHID);
    }

    // persistent bidirectional scan
    lstm_scan_kernel<<<128, 256>>>(Whh_f, Whh_b);

    // span pool + LN1
    span_pool_ln_kernel<<<BB*SS, 256>>>(heads, tails, ln1g, ln1b);

    // q,k,v = feat @ W + b : [512,1024] x [1024,1024]
    {
        dim3 grid(HHID/128, (BB*SS)/128), blk(256);
        sgemm_kernel<false><<<grid, blk>>>(p_feat, Wq, bq, p_q, BB*SS, HHID, HHID);
        sgemm_kernel<false><<<grid, blk>>>(p_feat, Wk, bk, p_k, BB*SS, HHID, HHID);
        sgemm_kernel<false><<<grid, blk>>>(p_feat, Wv, bv, p_v, BB*SS, HHID, HHID);
    }

    attn_kernel<<<BB*NHH, 256>>>(am);

    {
        dim3 grid(HHID/128, (BB*SS)/128), blk(256);
        sgemm_kernel<false><<<grid, blk>>>(p_ctx, Wo, bo, p_ao, BB*SS, HHID, HHID);
    }

    resid_ln_kernel<<<BB*SS, 256>>>(ln2g, ln2b);

    loss_terms_kernel<<<BB*SS, 128>>>(labels, wf, am, Wc, bc);

    final_loss_kernel<<<1, 256>>>((float*)d_out);
}

// round 4
// speedup vs baseline: 1.0790x; 1.0790x over previous
#include <cuda_runtime.h>
#include <math.h>

#define FULL 0xffffffffu
#define BB   16
#define TT   1024
#define HHID 1024
#define SS   32
#define CC   3
#define NHH  16
#define DHH  64
#define HH2  512
#define G4   2048

// ---------------- scratch ----------------
__device__ float g_xs_f[BB*TT*G4];
__device__ float g_xs_b[BB*TT*G4];
__device__ float g_enc [BB*TT*HHID];
__device__ float g_hbuf[2][2][BB][HH2];
__device__ float g_feat [BB*SS*HHID];
__device__ float g_q    [BB*SS*HHID];
__device__ float g_k    [BB*SS*HHID];
__device__ float g_v    [BB*SS*HHID];
__device__ float g_ctx  [BB*SS*HHID];
__device__ float g_ao   [BB*SS*HHID];
__device__ float g_feat2[BB*SS*HHID];
__device__ float g_terms[BB*SS*4];
__device__ unsigned g_bar_grp[8];
__device__ unsigned g_bar_master = 0;
__device__ unsigned g_bar_gen    = 0;

// ---------------- hierarchical grid barrier (128 CTAs) ----------------
__device__ __forceinline__ void grid_barrier()
{
    __threadfence();
    __syncthreads();
    if (threadIdx.x == 0) {
        volatile unsigned* genp = &g_bar_gen;
        const unsigned gen = *genp;
        const unsigned grp = blockIdx.x >> 4;
        if (atomicAdd(&g_bar_grp[grp], 1u) == 15u) {
            atomicExch(&g_bar_grp[grp], 0u);
            if (atomicAdd(&g_bar_master, 1u) == 7u) {
                atomicExch(&g_bar_master, 0u);
                __threadfence();
                atomicExch(&g_bar_gen, gen + 1u);
            }
        }
        while (*genp == gen) { }
    }
    __syncthreads();
}

// ---------------- tf32 helpers ----------------
__device__ __forceinline__ unsigned f2tf32(float x)
{
    unsigned u;
    asm("cvt.rna.tf32.f32 %0, %1;" : "=r"(u) : "f"(x));
    return u;
}

__device__ __forceinline__ void ldsm_x4(unsigned& r0, unsigned& r1, unsigned& r2, unsigned& r3,
                                        unsigned saddr)
{
    asm volatile("ldmatrix.sync.aligned.m8n8.x4.shared.b16 {%0,%1,%2,%3}, [%4];"
                 : "=r"(r0), "=r"(r1), "=r"(r2), "=r"(r3) : "r"(saddr));
}

__device__ __forceinline__ void mma_tf32(float* c, unsigned a0, unsigned a1, unsigned a2, unsigned a3,
                                         unsigned b0, unsigned b1)
{
    asm volatile(
        "mma.sync.aligned.m16n8k8.row.col.f32.tf32.tf32.f32 "
        "{%0,%1,%2,%3}, {%4,%5,%6,%7}, {%8,%9}, {%0,%1,%2,%3};"
        : "+f"(c[0]), "+f"(c[1]), "+f"(c[2]), "+f"(c[3])
        : "r"(a0), "r"(a1), "r"(a2), "r"(a3), "r"(b0), "r"(b1));
}

// ---------------- tf32 tensor-core GEMM: C[M,N] = A[M,K] @ B[N,K]^T + bias ----------------
// BM=128, BN=128, BK=16, 256 threads (8 warps: 2 m x 4 n), warp tile 64x32.
#define PAD 20
__global__ void __launch_bounds__(256)
tf32_gemm_tn(const float* __restrict__ A, const float* __restrict__ B,
             const float* __restrict__ bias, float* __restrict__ C,
             int M, int N, int K)
{
    __shared__ unsigned As[2][128][PAD];
    __shared__ unsigned Bs[2][128][PAD];
    const int tid  = threadIdx.x;
    const int warp = tid >> 5;
    const int lane = tid & 31;
    const int wm   = warp >> 2;   // 0..1
    const int wn   = warp & 3;    // 0..3
    const int bm   = blockIdx.y * 128;
    const int bn   = blockIdx.x * 128;

    float c[4][4][4];
#pragma unroll
    for (int i = 0; i < 4; i++)
#pragma unroll
        for (int j = 0; j < 4; j++)
#pragma unroll
            for (int r = 0; r < 4; r++) c[i][j][r] = 0.f;

    const int lr = tid >> 2;          // 0..63
    const int lc = (tid & 3) * 4;     // 0,4,8,12

    const float* Abase = A + (size_t)(bm + lr) * K + lc;
    const float* Bbase = B + (size_t)(bn + lr) * K + lc;

    // ldmatrix source addresses (same formula for A and B tiles)
    const int fr = lane & 15;                 // fragment row within 16-row block
    const int fc = ((lane >> 4) << 2);        // 0 or 4

    // prologue: fill buffer 0
    {
        float4 a0 = *(const float4*)(Abase);
        float4 a1 = *(const float4*)(Abase + (size_t)64 * K);
        float4 b0 = *(const float4*)(Bbase);
        float4 b1 = *(const float4*)(Bbase + (size_t)64 * K);
        As[0][lr][lc+0]=f2tf32(a0.x); As[0][lr][lc+1]=f2tf32(a0.y); As[0][lr][lc+2]=f2tf32(a0.z); As[0][lr][lc+3]=f2tf32(a0.w);
        As[0][lr+64][lc+0]=f2tf32(a1.x); As[0][lr+64][lc+1]=f2tf32(a1.y); As[0][lr+64][lc+2]=f2tf32(a1.z); As[0][lr+64][lc+3]=f2tf32(a1.w);
        Bs[0][lr][lc+0]=f2tf32(b0.x); Bs[0][lr][lc+1]=f2tf32(b0.y); Bs[0][lr][lc+2]=f2tf32(b0.z); Bs[0][lr][lc+3]=f2tf32(b0.w);
        Bs[0][lr+64][lc+0]=f2tf32(b1.x); Bs[0][lr+64][lc+1]=f2tf32(b1.y); Bs[0][lr+64][lc+2]=f2tf32(b1.z); Bs[0][lr+64][lc+3]=f2tf32(b1.w);
    }
    __syncthreads();

    const int KT = K / 16;
    for (int kt = 0; kt < KT; kt++) {
        const int cur = kt & 1;
        const int nxt = cur ^ 1;
        float4 na0, na1, nb0, nb1;
        if (kt + 1 < KT) {
            const float* Ap = Abase + (size_t)(kt + 1) * 16;
            const float* Bp = Bbase + (size_t)(kt + 1) * 16;
            na0 = *(const float4*)(Ap);
            na1 = *(const float4*)(Ap + (size_t)64 * K);
            nb0 = *(const float4*)(Bp);
            nb1 = *(const float4*)(Bp + (size_t)64 * K);
        }

#pragma unroll
        for (int ks = 0; ks < 2; ks++) {
            const int k0 = ks * 8 + fc;
            // B fragments for this warp: two x4 loads cover 4 n-frags
            unsigned b0a, b1a, b2a, b3a, b0b, b1b, b2b, b3b;
            {
                unsigned sa = (unsigned)__cvta_generic_to_shared(&Bs[cur][wn*32 + fr][k0]);
                ldsm_x4(b0a, b1a, b2a, b3a, sa);
                unsigned sb = (unsigned)__cvta_generic_to_shared(&Bs[cur][wn*32 + 16 + fr][k0]);
                ldsm_x4(b0b, b1b, b2b, b3b, sb);
            }
            // nfrag regs: nf0:{b0a,b2a} nf1:{b1a,b3a} nf2:{b0b,b2b} nf3:{b1b,b3b}
#pragma unroll
            for (int mf = 0; mf < 4; mf++) {
                unsigned a0, a1, a2, a3;
                unsigned sa = (unsigned)__cvta_generic_to_shared(&As[cur][wm*64 + mf*16 + fr][k0]);
                ldsm_x4(a0, a1, a2, a3, sa);
                mma_tf32(c[mf][0], a0, a1, a2, a3, b0a, b2a);
                mma_tf32(c[mf][1], a0, a1, a2, a3, b1a, b3a);
                mma_tf32(c[mf][2], a0, a1, a2, a3, b0b, b2b);
                mma_tf32(c[mf][3], a0, a1, a2, a3, b1b, b3b);
            }
        }

        if (kt + 1 < KT) {
            As[nxt][lr][lc+0]=f2tf32(na0.x); As[nxt][lr][lc+1]=f2tf32(na0.y); As[nxt][lr][lc+2]=f2tf32(na0.z); As[nxt][lr][lc+3]=f2tf32(na0.w);
            As[nxt][lr+64][lc+0]=f2tf32(na1.x); As[nxt][lr+64][lc+1]=f2tf32(na1.y); As[nxt][lr+64][lc+2]=f2tf32(na1.z); As[nxt][lr+64][lc+3]=f2tf32(na1.w);
            Bs[nxt][lr][lc+0]=f2tf32(nb0.x); Bs[nxt][lr][lc+1]=f2tf32(nb0.y); Bs[nxt][lr][lc+2]=f2tf32(nb0.z); Bs[nxt][lr][lc+3]=f2tf32(nb0.w);
            Bs[nxt][lr+64][lc+0]=f2tf32(nb1.x); Bs[nxt][lr+64][lc+1]=f2tf32(nb1.y); Bs[nxt][lr+64][lc+2]=f2tf32(nb1.z); Bs[nxt][lr+64][lc+3]=f2tf32(nb1.w);
        }
        __syncthreads();
    }

    // epilogue
    const int g  = lane >> 2;
    const int tg = lane & 3;
#pragma unroll
    for (int mf = 0; mf < 4; mf++) {
        const int row0 = bm + wm*64 + mf*16 + g;
#pragma unroll
        for (int nf = 0; nf < 4; nf++) {
            const int col0 = bn + wn*32 + nf*8 + 2*tg;
            const float2 bv = *(const float2*)&bias[col0];
            float2 v0 = make_float2(c[mf][nf][0] + bv.x, c[mf][nf][1] + bv.y);
            float2 v1 = make_float2(c[mf][nf][2] + bv.x, c[mf][nf][3] + bv.y);
            *(float2*)&C[(size_t)row0 * N + col0]       = v0;
            *(float2*)&C[(size_t)(row0 + 8) * N + col0] = v1;
        }
    }
}

// ---------------- fp32 SGEMM (small QKV/O GEMMs), B is (K,N) ----------------
__global__ void __launch_bounds__(256)
sgemm_kn(const float* __restrict__ A, const float* __restrict__ B,
         const float* __restrict__ bias, float* __restrict__ C,
         int M, int N, int K)
{
    const int BM = 128, BN = 128, BK = 8, TM = 8, TN = 8;
    __shared__ float As[BK][BM];
    __shared__ float Bs[BK][BN];
    const int tid = threadIdx.x;
    const int bm = blockIdx.y * BM;
    const int bn = blockIdx.x * BN;
    const int tx = tid & 15;
    const int ty = tid >> 4;

    float acc[TM][TN];
#pragma unroll
    for (int i = 0; i < TM; i++)
#pragma unroll
        for (int j = 0; j < TN; j++) acc[i][j] = 0.f;

    const int aRow = (tid * 4) / BK;
    const int aCol = (tid * 4) % BK;
    const int bRow = (tid * 4) / BN;
    const int bCol = (tid * 4) % BN;

    const float* Aptr = A + (size_t)(bm + aRow) * K + aCol;
    const float* Bptr = B + (size_t)bRow * N + (bn + bCol);

    for (int k0 = 0; k0 < K; k0 += BK) {
        const float4 av = *(const float4*)Aptr; Aptr += BK;
        As[aCol + 0][aRow] = av.x;
        As[aCol + 1][aRow] = av.y;
        As[aCol + 2][aRow] = av.z;
        As[aCol + 3][aRow] = av.w;
        const float4 bv = *(const float4*)Bptr; Bptr += (size_t)BK * N;
        *(float4*)&Bs[bRow][bCol] = bv;
        __syncthreads();
#pragma unroll
        for (int kk = 0; kk < BK; kk++) {
            float ar[TM], br[TN];
#pragma unroll
            for (int h = 0; h < 2; h++) {
                const float4 t4 = *(const float4*)&As[kk][h * 64 + ty * 4];
                ar[h*4+0]=t4.x; ar[h*4+1]=t4.y; ar[h*4+2]=t4.z; ar[h*4+3]=t4.w;
            }
#pragma unroll
            for (int h = 0; h < 2; h++) {
                const float4 t4 = *(const float4*)&Bs[kk][h * 64 + tx * 4];
                br[h*4+0]=t4.x; br[h*4+1]=t4.y; br[h*4+2]=t4.z; br[h*4+3]=t4.w;
            }
#pragma unroll
            for (int i = 0; i < TM; i++)
#pragma unroll
                for (int j = 0; j < TN; j++)
                    acc[i][j] += ar[i] * br[j];
        }
        __syncthreads();
    }

#pragma unroll
    for (int i = 0; i < TM; i++) {
        const int row = bm + (i / 4) * 64 + ty * 4 + (i % 4);
#pragma unroll
        for (int j = 0; j < TN; j++) {
            const int col = bn + (j / 4) * 64 + tx * 4 + (j % 4);
            C[(size_t)row * N + col] = acc[i][j] + bias[col];
        }
    }
}

// ---------------- f32x2 packed FMA ----------------
__device__ __forceinline__ void fma2(unsigned long long& d, unsigned long long a, unsigned long long b)
{
    asm("fma.rn.f32x2 %0, %1, %2, %0;" : "+l"(d) : "l"(a), "l"(b));
}

union U2F4 { float4 f4; unsigned long long u[2]; };

// ---------------- persistent bidirectional LSTM scan ----------------
__global__ void __launch_bounds__(256)
lstm_scan_kernel(const float* __restrict__ Whh_f, const float* __restrict__ Whh_b)
{
    const int cid  = blockIdx.x;
    const int dir  = cid >> 6;
    const int ug   = cid & 63;
    const int warp = threadIdx.x >> 5;
    const int lane = threadIdx.x & 31;
    const int gt   = lane >> 3;
    const int kc   = lane & 7;
    const int u    = ug * 8 + warp;
    const int grow = gt * HH2 + u;

    const float* __restrict__ Whh = dir ? Whh_b : Whh_f;
    const float* __restrict__ xs  = dir ? g_xs_b : g_xs_f;

    U2F4 w[16];
#pragma unroll
    for (int j = 0; j < 16; j++)
        w[j].f4 = *(const float4*)&Whh[(size_t)grow * HH2 + (kc + 8 * j) * 4];

    __shared__ float h_sh[BB][HH2];

    float c_state[BB];
#pragma unroll
    for (int b = 0; b < BB; b++) c_state[b] = 0.f;

    for (int s = 0; s < TT; s++) {
        const int t = dir ? (TT - 1 - s) : s;

        if (s == 0) {
            for (int i = threadIdx.x; i < BB * HH2; i += 256)
                ((float*)h_sh)[i] = 0.f;
        } else {
            const float* hg = &g_hbuf[dir][(s - 1) & 1][0][0];
            for (int i = threadIdx.x * 4; i < BB * HH2; i += 1024)
                *(float4*)&((float*)h_sh)[i] = *(const float4*)&hg[i];
        }

        float xsv[BB];
        if (kc == 0) {
#pragma unroll
            for (int b = 0; b < BB; b++)
                xsv[b] = xs[(size_t)(b * TT + t) * G4 + grow];
        }
        __syncthreads();

        unsigned long long acc2[BB];
#pragma unroll
        for (int b = 0; b < BB; b++) acc2[b] = 0ull;

#pragma unroll
        for (int j = 0; j < 16; j++) {
            const int kbase = (kc + 8 * j) * 4;
#pragma unroll
            for (int b = 0; b < BB; b++) {
                U2F4 hv;
                hv.f4 = *(const float4*)&h_sh[b][kbase];
                fma2(acc2[b], w[j].u[0], hv.u[0]);
                fma2(acc2[b], w[j].u[1], hv.u[1]);
            }
        }

        float acc[BB];
#pragma unroll
        for (int b = 0; b < BB; b++) {
            union { unsigned long long u; float2 f; } cv;
            cv.u = acc2[b];
            acc[b] = cv.f.x + cv.f.y;
            acc[b] += __shfl_down_sync(FULL, acc[b], 4);
            acc[b] += __shfl_down_sync(FULL, acc[b], 2);
            acc[b] += __shfl_down_sync(FULL, acc[b], 1);
        }

        float gv[BB];
#pragma unroll
        for (int b = 0; b < BB; b++) gv[b] = 0.f;
        if (kc == 0) {
#pragma unroll
            for (int b = 0; b < BB; b++) {
                const float x = acc[b] + xsv[b];
                gv[b] = (gt == 2) ? tanhf(x) : (1.f / (1.f + expf(-x)));
            }
        }

#pragma unroll
        for (int b = 0; b < BB; b++) {
            const float iv = __shfl_sync(FULL, gv[b], 0);
            const float fv = __shfl_sync(FULL, gv[b], 8);
            const float gg = __shfl_sync(FULL, gv[b], 16);
            const float ov = __shfl_sync(FULL, gv[b], 24);
            if (lane == 0) {
                const float cn = fv * c_state[b] + iv * gg;
                c_state[b] = cn;
                const float hn = ov * tanhf(cn);
                g_hbuf[dir][s & 1][b][u] = hn;
                g_enc[(size_t)(b * TT + t) * HHID + dir * HH2 + u] = hn;
            }
        }

        grid_barrier();
    }
}

// ---------------- span mean-pool + LayerNorm ----------------
__global__ void __launch_bounds__(256)
span_pool_ln_kernel(const int* __restrict__ heads, const int* __restrict__ tails,
                    const float* __restrict__ lng, const float* __restrict__ lnb)
{
    const int r = blockIdx.x;
    const int b = r >> 5;
    int p0 = heads[r] + 1; if (p0 < 0) p0 = 0;
    int p1 = tails[r];     if (p1 > TT) p1 = TT;
    const int tid = threadIdx.x;
    const int d = tid * 4;

    float s0=0,s1=0,s2=0,s3=0;
    for (int p = p0; p < p1; p++) {
        const float4 vv = *(const float4*)&g_enc[(size_t)(b * TT + p) * HHID + d];
        s0 += vv.x; s1 += vv.y; s2 += vv.z; s3 += vv.w;
    }
    int cnt = p1 - p0; if (cnt < 1) cnt = 1;
    const float inv = 1.f / (float)cnt;
    const float v0=s0*inv, v1=s1*inv, v2=s2*inv, v3=s3*inv;

    __shared__ float red[256];
    __shared__ float stats[2];
    red[tid] = v0+v1+v2+v3;
    __syncthreads();
    for (int st = 128; st > 0; st >>= 1) { if (tid < st) red[tid] += red[tid+st]; __syncthreads(); }
    if (tid == 0) stats[0] = red[0] * (1.f / HHID);
    __syncthreads();
    const float mean = stats[0];
    const float q0=v0-mean, q1=v1-mean, q2=v2-mean, q3=v3-mean;
    red[tid] = q0*q0+q1*q1+q2*q2+q3*q3;
    __syncthreads();
    for (int st = 128; st > 0; st >>= 1) { if (tid < st) red[tid] += red[tid+st]; __syncthreads(); }
    if (tid == 0) stats[1] = rsqrtf(red[0] * (1.f / HHID) + 1e-7f);
    __syncthreads();
    const float rstd = stats[1];
    float* out = &g_feat[(size_t)r * HHID + d];
    out[0] = q0*rstd*lng[d+0] + lnb[d+0];
    out[1] = q1*rstd*lng[d+1] + lnb[d+1];
    out[2] = q2*rstd*lng[d+2] + lnb[d+2];
    out[3] = q3*rstd*lng[d+3] + lnb[d+3];
}

// ---------------- attention ----------------
__global__ void __launch_bounds__(256)
attn_kernel(const int* __restrict__ am)
{
    const int bh = blockIdx.x;
    const int b = bh >> 4;
    const int h = bh & 15;
    __shared__ float qs[SS][DHH], ks[SS][DHH], vs[SS][DHH];
    __shared__ float sc[SS][SS + 1];
    const int tid = threadIdx.x;

    for (int i = tid; i < SS * DHH; i += 256) {
        const int s = i >> 6, d = i & 63;
        const size_t off = (size_t)(b * SS + s) * HHID + h * DHH + d;
        qs[s][d] = g_q[off];
        ks[s][d] = g_k[off];
        vs[s][d] = g_v[off];
    }
    __syncthreads();

    for (int i = tid; i < SS * SS; i += 256) {
        const int qq = i >> 5, kk = i & 31;
        float a = 0.f;
#pragma unroll
        for (int d = 0; d < DHH; d++) a += qs[qq][d] * ks[kk][d];
        const bool valid = (am[b * SS + qq] != 0) && (am[b * SS + kk] != 0);
        sc[qq][kk] = valid ? a * 0.125f : -1e9f;
    }
    __syncthreads();

    const int wid = tid >> 5, lane = tid & 31;
    for (int r = wid; r < SS; r += 8) {
        const float val = sc[r][lane];
        float m = val;
#pragma unroll
        for (int o = 16; o > 0; o >>= 1) m = fmaxf(m, __shfl_xor_sync(FULL, m, o));
        const float e = expf(val - m);
        float sum = e;
#pragma unroll
        for (int o = 16; o > 0; o >>= 1) sum += __shfl_xor_sync(FULL, sum, o);
        sc[r][lane] = e / sum;
    }
    __syncthreads();

    for (int i = tid; i < SS * DHH; i += 256) {
        const int qq = i >> 6, d = i & 63;
        float a = 0.f;
#pragma unroll
        for (int kk = 0; kk < SS; kk++) a += sc[qq][kk] * vs[kk][d];
        g_ctx[(size_t)(b * SS + qq) * HHID + h * DHH + d] = a;
    }
}

// ---------------- residual + LayerNorm ----------------
__global__ void __launch_bounds__(256)
resid_ln_kernel(const float* __restrict__ lng, const float* __restrict__ lnb)
{
    const int r = blockIdx.x;
    const int tid = threadIdx.x;
    const int d = tid * 4;
    const size_t base = (size_t)r * HHID + d;
    const float4 a = *(const float4*)&g_ao[base];
    const float4 f = *(const float4*)&g_feat[base];
    const float v0=a.x+f.x, v1=a.y+f.y, v2=a.z+f.z, v3=a.w+f.w;

    __shared__ float red[256];
    __shared__ float stats[2];
    red[tid] = v0+v1+v2+v3;
    __syncthreads();
    for (int st = 128; st > 0; st >>= 1) { if (tid < st) red[tid] += red[tid+st]; __syncthreads(); }
    if (tid == 0) stats[0] = red[0] * (1.f / HHID);
    __syncthreads();
    const float mean = stats[0];
    const float q0=v0-mean, q1=v1-mean, q2=v2-mean, q3=v3-mean;
    red[tid] = q0*q0+q1*q1+q2*q2+q3*q3;
    __syncthreads();
    for (int st = 128; st > 0; st >>= 1) { if (tid < st) red[tid] += red[tid+st]; __syncthreads(); }
    if (tid == 0) stats[1] = rsqrtf(red[0] * (1.f / HHID) + 1e-7f);
    __syncthreads();
    const float rstd = stats[1];
    float* out = &g_feat2[base];
    out[0] = q0*rstd*lng[d+0] + lnb[d+0];
    out[1] = q1*rstd*lng[d+1] + lnb[d+1];
    out[2] = q2*rstd*lng[d+2] + lnb[d+2];
    out[3] = q3*rstd*lng[d+3] + lnb[d+3];
}

// ---------------- classifier + per-span loss terms ----------------
__global__ void __launch_bounds__(128)
loss_terms_kernel(const int* __restrict__ labels, const float* __restrict__ wf,
                  const int* __restrict__ am,
                  const float* __restrict__ Wc, const float* __restrict__ bc)
{
    const int r = blockIdx.x;
    const int tid = threadIdx.x;
    const float* row = &g_feat2[(size_t)r * HHID];
    float d0=0, d1=0, d2=0;
    for (int i = tid; i < HHID; i += 128) {
        const float x = row[i];
        d0 += x * Wc[i*3+0];
        d1 += x * Wc[i*3+1];
        d2 += x * Wc[i*3+2];
    }
    __shared__ float r0[128], r1[128], r2[128];
    r0[tid]=d0; r1[tid]=d1; r2[tid]=d2;
    __syncthreads();
    for (int st = 64; st > 0; st >>= 1) {
        if (tid < st) { r0[tid]+=r0[tid+st]; r1[tid]+=r1[tid+st]; r2[tid]+=r2[tid+st]; }
        __syncthreads();
    }
    if (tid == 0) {
        const float z0 = r0[0]+bc[0], z1 = r1[0]+bc[1], z2 = r2[0]+bc[2];
        const float m = fmaxf(z0, fmaxf(z1, z2));
        const float e0 = expf(z0-m), e1 = expf(z1-m), e2 = expf(z2-m);
        const float lse = m + logf(e0+e1+e2);
        const int lab = labels[r];
        const bool valid = lab >= 0;
        const int lc = valid ? lab : 0;
        const float zl = (lc==0) ? z0 : ((lc==1) ? z1 : z2);
        const float logp = zl - lse;
        const float pt = expf(logp);
        const float spanm = ((am[r]!=0) && valid) ? 1.f : 0.f;
        const float vm = valid ? 1.f : 0.f;
        const float omp = 1.f - pt;
        g_terms[r*4+0] = (-logp * wf[r]) * spanm;
        g_terms[r*4+1] = spanm;
        g_terms[r*4+2] = (-(omp*omp) * logp) * vm;
        g_terms[r*4+3] = vm;
    }
}

__global__ void __launch_bounds__(256)
final_loss_kernel(float* __restrict__ out)
{
    const int tid = threadIdx.x;
    float a0=0,a1=0,a2=0,a3=0;
    for (int r = tid; r < BB*SS; r += 256) {
        a0 += g_terms[r*4+0]; a1 += g_terms[r*4+1];
        a2 += g_terms[r*4+2]; a3 += g_terms[r*4+3];
    }
    __shared__ float s0[256], s1[256], s2[256], s3[256];
    s0[tid]=a0; s1[tid]=a1; s2[tid]=a2; s3[tid]=a3;
    __syncthreads();
    for (int st = 128; st > 0; st >>= 1) {
        if (tid < st) { s0[tid]+=s0[tid+st]; s1[tid]+=s1[tid+st]; s2[tid]+=s2[tid+st]; s3[tid]+=s3[tid+st]; }
        __syncthreads();
    }
    if (tid == 0)
        out[0] = s0[0] / fmaxf(s1[0], 1.f) + s2[0] / fmaxf(s3[0], 1.f);
}

// ---------------- launch ----------------
extern "C" void kernel_launch(void* const* d_in, const int* in_sizes, int n_in,
                              void* d_out, int out_size)
{
    const float* hs     = (const float*)d_in[0];
    const int*   heads  = (const int*)  d_in[1];
    const int*   tails  = (const int*)  d_in[2];
    const int*   am     = (const int*)  d_in[3];
    const int*   labels = (const int*)  d_in[4];
    const float* wf     = (const float*)d_in[5];
    const float* Wih_f  = (const float*)d_in[6];
    const float* Whh_f  = (const float*)d_in[7];
    const float* b_f    = (const float*)d_in[8];
    const float* Wih_b  = (const float*)d_in[9];
    const float* Whh_b  = (const float*)d_in[10];
    const float* b_b    = (const float*)d_in[11];
    const float* ln1g   = (const float*)d_in[12];
    const float* ln1b   = (const float*)d_in[13];
    const float* Wq     = (const float*)d_in[14];
    const float* bq     = (const float*)d_in[15];
    const float* Wk     = (const float*)d_in[16];
    const float* bk     = (const float*)d_in[17];
    const float* Wv     = (const float*)d_in[18];
    const float* bv     = (const float*)d_in[19];
    const float* Wo     = (const float*)d_in[20];
    const float* bo     = (const float*)d_in[21];
    const float* ln2g   = (const float*)d_in[22];
    const float* ln2b   = (const float*)d_in[23];
    const float* Wc     = (const float*)d_in[24];
    const float* bc     = (const float*)d_in[25];

    float *p_xs_f, *p_xs_b, *p_feat, *p_q, *p_k, *p_v, *p_ctx, *p_ao;
    cudaGetSymbolAddress((void**)&p_xs_f,  g_xs_f);
    cudaGetSymbolAddress((void**)&p_xs_b,  g_xs_b);
    cudaGetSymbolAddress((void**)&p_feat,  g_feat);
    cudaGetSymbolAddress((void**)&p_q,     g_q);
    cudaGetSymbolAddress((void**)&p_k,     g_k);
    cudaGetSymbolAddress((void**)&p_v,     g_v);
    cudaGetSymbolAddress((void**)&p_ctx,   g_ctx);
    cudaGetSymbolAddress((void**)&p_ao,    g_ao);

    // input projections on tensor cores (tf32): [16384,1024] x [2048,1024]^T
    {
        dim3 grid(G4/128, (BB*TT)/128), blk(256);
        tf32_gemm_tn<<<grid, blk>>>(hs, Wih_f, b_f, p_xs_f, BB*TT, G4, HHID);
        tf32_gemm_tn<<<grid, blk>>>(hs, Wih_b, b_b, p_xs_b, BB*TT, G4, HHID);
    }

    // persistent bidirectional scan
    lstm_scan_kernel<<<128, 256>>>(Whh_f, Whh_b);

    // span pool + LN1
    span_pool_ln_kernel<<<BB*SS, 256>>>(heads, tails, ln1g, ln1b);

    // q,k,v = feat @ W + b : [512,1024] x [1024,1024]
    {
        dim3 grid(HHID/128, (BB*SS)/128), blk(256);
        sgemm_kn<<<grid, blk>>>(p_feat, Wq, bq, p_q, BB*SS, HHID, HHID);
        sgemm_kn<<<grid, blk>>>(p_feat, Wk, bk, p_k, BB*SS, HHID, HHID);
        sgemm_kn<<<grid, blk>>>(p_feat, Wv, bv, p_v, BB*SS, HHID, HHID);
    }

    attn_kernel<<<BB*NHH, 256>>>(am);

    {
        dim3 grid(HHID/128, (BB*SS)/128), blk(256);
        sgemm_kn<<<grid, blk>>>(p_ctx, Wo, bo, p_ao, BB*SS, HHID, HHID);
    }

    resid_ln_kernel<<<BB*SS, 256>>>(ln2g, ln2b);

    loss_terms_kernel<<<BB*SS, 128>>>(labels, wf, am, Wc, bc);

    final_loss_kernel<<<1, 256>>>((float*)d_out);
}